// round 6
// baseline (speedup 1.0000x reference)
#include <cuda_runtime.h>
#include <cstdint>

#define NT 512   // 16 warps, one block, one SM

using u64 = unsigned long long;

__device__ __forceinline__ u64 pk(float lo, float hi) {
    u64 r; asm("mov.b64 %0, {%1,%2};" : "=l"(r) : "f"(lo), "f"(hi)); return r;
}
__device__ __forceinline__ void upk(u64 p, float& lo, float& hi) {
    asm("mov.b64 {%0,%1}, %2;" : "=f"(lo), "=f"(hi) : "l"(p));
}
__device__ __forceinline__ u64 fma2(u64 a, u64 b, u64 c) {
    u64 d; asm("fma.rn.f32x2 %0, %1, %2, %3;" : "=l"(d) : "l"(a), "l"(b), "l"(c)); return d;
}
__device__ __forceinline__ u64 mul2(u64 a, u64 b) {
    u64 d; asm("mul.rn.f32x2 %0, %1, %2;" : "=l"(d) : "l"(a), "l"(b)); return d;
}
__device__ __forceinline__ float frcp(float x) {
    float r; asm("rcp.approx.f32 %0, %1;" : "=f"(r) : "f"(x)); return r;
}
__device__ __forceinline__ float flg2(float x) {
    float r; asm("lg2.approx.f32 %0, %1;" : "=f"(r) : "f"(x)); return r;
}
__device__ __forceinline__ float fsqrt_ap(float x) {
    float r; asm("sqrt.approx.f32 %0, %1;" : "=f"(r) : "f"(x)); return r;
}

__global__ void __launch_bounds__(NT, 1)
sgd_filter_design_kernel(const float* __restrict__ sos_init,
                         const float* __restrict__ target_dB,
                         float* __restrict__ out)
{
    // coefficient-major filter state: cof[c][s], c in {b0,b1,b2,a0,a1,a2}
    __shared__ __align__(16) float  cof[6][16];
    // packed trig for freq pairs (f, f+256):
    //   ptA[f] = {c1_f, c1_{f+256}, s1_f, s1_{f+256}}
    //   ptB[f] = {c2_f, c2_{f+256}, s2_f, s2_{f+256}}
    __shared__ __align__(16) float4 ptA[256];
    __shared__ __align__(16) float4 ptB[256];
    __shared__ __align__(8)  float  pcc[512];  // packed cc pairs: [2f]=cc_f, [2f+1]=cc_{f+256}
    __shared__ float grad[96];

    const int tid  = threadIdx.x;
    const int warp = tid >> 5;
    const int lane = tid & 31;

    if (tid < 96) cof[tid % 6][tid / 6] = sos_init[tid];

    // Per-thread trig (thread tid owns freq tid), double precision once.
    float tc1, ts1, tc2, ts2, tgt;
    {
        double w = (double)tid * (3.14159265358979323846 / 511.0);
        tc1 = (float)cos(w);        ts1 = (float)sin(w);
        tc2 = (float)cos(2.0 * w);  ts2 = (float)sin(2.0 * w);
        tgt = target_dB[tid];
        int i = tid & 255;
        if (tid < 256) {
            ptA[i].x = tc1; ptA[i].z = ts1;
            ptB[i].x = tc2; ptB[i].z = ts2;
        } else {
            ptA[i].y = tc1; ptA[i].w = ts1;
            ptB[i].y = tc2; ptB[i].w = ts2;
        }
    }
    // packed broadcasts of own-freq trig for pass 1
    const u64 pc1 = pk(tc1, tc1), ps1 = pk(ts1, ts1);
    const u64 pc2 = pk(tc2, tc2), ps2 = pk(ts2, ts2);
    const int ccslot = (tid < 256) ? (2 * tid) : (2 * (tid - 256) + 1);
    __syncthreads();

    const float KC  = 40.0f / (512.0f * 2.30258509299404568402f); // 2/n * 20/ln10
    const float DB2 = 6.02059991327962390427f;                    // 20*log10(2)
    const float EPS = 1e-8f;
    const float LR  = 0.1f;

    for (int it = 0; it < 1000; ++it) {
        // ---------- Pass 1: |H|^2 product for own freq, sections packed 2-wide.
        // Ratio taken per 4-section group (bounded range, no underflow).
        u64 accR = pk(1.0f, 1.0f);
        const float4* c4 = (const float4*)cof;   // row c = c4[c*4 .. c*4+3]
#pragma unroll
        for (int p = 0; p < 4; ++p) {
            float4 b0v = c4[0*4+p], b1v = c4[1*4+p], b2v = c4[2*4+p];
            float4 a0v = c4[3*4+p], a1v = c4[4*4+p], a2v = c4[5*4+p];
            u64 prodB, prodA;
            {   // sections 4p, 4p+1
                u64 b0 = pk(b0v.x, b0v.y), b1 = pk(b1v.x, b1v.y), b2 = pk(b2v.x, b2v.y);
                u64 a0 = pk(a0v.x, a0v.y), a1 = pk(a1v.x, a1v.y), a2 = pk(a2v.x, a2v.y);
                u64 Br = fma2(b2, pc2, fma2(b1, pc1, b0));
                u64 Bp = fma2(b2, ps2, mul2(b1, ps1));   // = -Im(B)
                u64 Ar = fma2(a2, pc2, fma2(a1, pc1, a0));
                u64 Ap = fma2(a2, ps2, mul2(a1, ps1));
                prodB = fma2(Bp, Bp, mul2(Br, Br));
                prodA = fma2(Ap, Ap, mul2(Ar, Ar));
            }
            {   // sections 4p+2, 4p+3
                u64 b0 = pk(b0v.z, b0v.w), b1 = pk(b1v.z, b1v.w), b2 = pk(b2v.z, b2v.w);
                u64 a0 = pk(a0v.z, a0v.w), a1 = pk(a1v.z, a1v.w), a2 = pk(a2v.z, a2v.w);
                u64 Br = fma2(b2, pc2, fma2(b1, pc1, b0));
                u64 Bp = fma2(b2, ps2, mul2(b1, ps1));
                u64 Ar = fma2(a2, pc2, fma2(a1, pc1, a0));
                u64 Ap = fma2(a2, ps2, mul2(a1, ps1));
                prodB = mul2(prodB, fma2(Bp, Bp, mul2(Br, Br)));
                prodA = mul2(prodA, fma2(Ap, Ap, mul2(Ar, Ar)));
            }
            float al, ah; upk(prodA, al, ah);
            accR = mul2(accR, mul2(prodB, pk(frcp(al), frcp(ah))));
        }
        {
            float rlo, rhi; upk(accR, rlo, rhi);
            float pP  = rlo * rhi;                 // |H|^2
            float mag = fsqrt_ap(pP);
            float mpe = mag + EPS;
            float dB  = DB2 * flg2(mpe);
            pcc[ccslot] = KC * (dB - tgt) * (mag * frcp(mpe));
        }
        __syncthreads();

        // ---------- Pass 2: warp s integrates section s, freqs packed (f, f+256)
        {
            const int s = warp;
            float sb0 = cof[0][s], sb1 = cof[1][s], sb2 = cof[2][s];
            float sa0 = cof[3][s], sa1 = cof[4][s], sa2 = cof[5][s];
            u64 b0 = pk(sb0, sb0), b1 = pk(sb1, sb1), b2 = pk(sb2, sb2);
            u64 a0 = pk(sa0, sa0), a1 = pk(sa1, sa1), a2 = pk(sa2, sa2);
            u64 G0 = 0, G1 = 0, G2 = 0, H3 = 0, H4 = 0, H5 = 0;
#pragma unroll
            for (int k = 0; k < 8; ++k) {
                int f = k * 32 + lane;
                float4 tA = ptA[f], tB = ptB[f];
                u64 c1 = pk(tA.x, tA.y), s1 = pk(tA.z, tA.w);
                u64 c2 = pk(tB.x, tB.y), s2 = pk(tB.z, tB.w);
                u64 cc = *(const u64*)&pcc[2 * f];
                u64 Br = fma2(b2, c2, fma2(b1, c1, b0));
                u64 Bp = fma2(b2, s2, mul2(b1, s1));
                u64 Ar = fma2(a2, c2, fma2(a1, c1, a0));
                u64 Ap = fma2(a2, s2, mul2(a1, s1));
                u64 nB = fma2(Bp, Bp, mul2(Br, Br));
                u64 nA = fma2(Ap, Ap, mul2(Ar, Ar));
                float xl, xh, yl, yh; upk(nB, xl, xh); upk(nA, yl, yh);
                u64 cB = mul2(cc, pk(frcp(xl), frcp(xh)));
                u64 cA = mul2(cc, pk(frcp(yl), frcp(yh)));   // positive; negate at end
                G0 = fma2(cB, Br, G0);
                G1 = fma2(cB, fma2(s1, Bp, mul2(c1, Br)), G1);  // c1*Br - s1*Bi, Bi=-Bp
                G2 = fma2(cB, fma2(s2, Bp, mul2(c2, Br)), G2);
                H3 = fma2(cA, Ar, H3);
                H4 = fma2(cA, fma2(s1, Ap, mul2(c1, Ar)), H4);
                H5 = fma2(cA, fma2(s2, Ap, mul2(c2, Ar)), H5);
            }
            float g0, g1, g2, g3, g4, g5, u, v;
            upk(G0, u, v); g0 = u + v;
            upk(G1, u, v); g1 = u + v;
            upk(G2, u, v); g2 = u + v;
            upk(H3, u, v); g3 = -(u + v);
            upk(H4, u, v); g4 = -(u + v);
            upk(H5, u, v); g5 = -(u + v);
#pragma unroll
            for (int o = 16; o > 0; o >>= 1) {
                g0 += __shfl_xor_sync(0xffffffffu, g0, o);
                g1 += __shfl_xor_sync(0xffffffffu, g1, o);
                g2 += __shfl_xor_sync(0xffffffffu, g2, o);
                g3 += __shfl_xor_sync(0xffffffffu, g3, o);
                g4 += __shfl_xor_sync(0xffffffffu, g4, o);
                g5 += __shfl_xor_sync(0xffffffffu, g5, o);
            }
            if (lane == 0) {
                grad[s * 6 + 0] = g0;
                grad[s * 6 + 1] = g1;
                grad[s * 6 + 2] = g2;
                grad[s * 6 + 3] = g3;
                grad[s * 6 + 4] = g4;
                grad[s * 6 + 5] = g5;
            }
        }
        __syncthreads();

        // ---------- SGD update ----------
        if (tid < 96) cof[tid % 6][tid / 6] -= LR * grad[tid];
        __syncthreads();
    }

    if (tid < 96) out[tid] = cof[tid % 6][tid / 6];
}

extern "C" void kernel_launch(void* const* d_in, const int* in_sizes, int n_in,
                              void* d_out, int out_size) {
    const float* sos_init  = (const float*)d_in[0];   // [16,6] = 96 floats
    const float* target_dB = (const float*)d_in[1];   // [512]
    float* out = (float*)d_out;                       // [16,6] = 96 floats
    sgd_filter_design_kernel<<<1, NT>>>(sos_init, target_dB, out);
}

// round 7
// speedup vs baseline: 1.0698x; 1.0698x over previous
#include <cuda_runtime.h>
#include <cstdint>

#define NT 512   // 16 warps, one block, one SM

using u64 = unsigned long long;

__device__ __forceinline__ u64 pk(float lo, float hi) {
    u64 r; asm("mov.b64 %0, {%1,%2};" : "=l"(r) : "f"(lo), "f"(hi)); return r;
}
__device__ __forceinline__ void upk(u64 p, float& lo, float& hi) {
    asm("mov.b64 {%0,%1}, %2;" : "=f"(lo), "=f"(hi) : "l"(p));
}
__device__ __forceinline__ u64 fma2(u64 a, u64 b, u64 c) {
    u64 d; asm("fma.rn.f32x2 %0, %1, %2, %3;" : "=l"(d) : "l"(a), "l"(b), "l"(c)); return d;
}
__device__ __forceinline__ u64 mul2(u64 a, u64 b) {
    u64 d; asm("mul.rn.f32x2 %0, %1, %2;" : "=l"(d) : "l"(a), "l"(b)); return d;
}
__device__ __forceinline__ float frcp(float x) {
    float r; asm("rcp.approx.f32 %0, %1;" : "=f"(r) : "f"(x)); return r;
}
__device__ __forceinline__ float flg2(float x) {
    float r; asm("lg2.approx.f32 %0, %1;" : "=f"(r) : "f"(x)); return r;
}
__device__ __forceinline__ float fsqrt_ap(float x) {
    float r; asm("sqrt.approx.f32 %0, %1;" : "=f"(r) : "f"(x)); return r;
}

__global__ void __launch_bounds__(NT, 1)
sgd_filter_design_kernel(const float* __restrict__ sos_init,
                         const float* __restrict__ target_dB,
                         float* __restrict__ out)
{
    // coefficient-major state: cof[c][s]; adjacent sections form 8B-aligned pairs
    __shared__ __align__(16) float cof[6][16];
    // pre-packed trig: each u64 holds (freq f, freq f+256)
    __shared__ __align__(8) u64 tc1p[256], ts1p[256], tc2p[256], ts2p[256];
    __shared__ __align__(8) float pcc[512];   // cc pairs: [2f]=cc_f, [2f+1]=cc_{f+256}

    const int tid  = threadIdx.x;
    const int warp = tid >> 5;
    const int lane = tid & 31;

    if (tid < 96) cof[tid % 6][tid / 6] = sos_init[tid];

    // Per-thread trig (thread tid owns freq tid), double precision once.
    float tc1, ts1, tc2, ts2, tgt;
    {
        double w = (double)tid * (3.14159265358979323846 / 511.0);
        tc1 = (float)cos(w);        ts1 = (float)sin(w);
        tc2 = (float)cos(2.0 * w);  ts2 = (float)sin(2.0 * w);
        tgt = target_dB[tid];
        int i = tid & 255;
        int h = (tid >> 8) & 1;                 // 0 = lo half, 1 = hi half
        ((float*)&tc1p[i])[h] = tc1;  ((float*)&ts1p[i])[h] = ts1;
        ((float*)&tc2p[i])[h] = tc2;  ((float*)&ts2p[i])[h] = ts2;
    }
    // packed broadcasts of own-freq trig for pass 1 (constants, live in regs)
    const u64 pc1 = pk(tc1, tc1), ps1 = pk(ts1, ts1);
    const u64 pc2 = pk(tc2, tc2), ps2 = pk(ts2, ts2);
    const int ccslot = ((tid & 255) << 1) | ((tid >> 8) & 1);
    __syncthreads();

    const float KC  = 40.0f / (512.0f * 2.30258509299404568402f); // 2/n * 20/ln10
    const float DB2 = 6.02059991327962390427f;                    // 20*log10(2)
    const float EPS = 1e-8f;
    const float LR  = 0.1f;

    const u64* cofp = (const u64*)cof;        // row c = cofp[c*8 .. c*8+7]
    const u64* pccp = (const u64*)pcc;

    for (int it = 0; it < 1000; ++it) {
        // ---------- Pass 1: |H|^2 for own freq; sections packed 2-wide,
        // ratio per 4-section group (bounded range; same grouping as R6 PASS).
        u64 accR = pk(1.0f, 1.0f);
#pragma unroll
        for (int p = 0; p < 4; ++p) {
            u64 prodB, prodA;
            {   // sections (4p, 4p+1): direct LDS.64 pair loads, no packing movs
                u64 b0 = cofp[0*8 + 2*p], b1 = cofp[1*8 + 2*p], b2 = cofp[2*8 + 2*p];
                u64 a0 = cofp[3*8 + 2*p], a1 = cofp[4*8 + 2*p], a2 = cofp[5*8 + 2*p];
                u64 Br = fma2(b2, pc2, fma2(b1, pc1, b0));
                u64 Bp = fma2(b2, ps2, mul2(b1, ps1));   // = -Im(B)
                u64 Ar = fma2(a2, pc2, fma2(a1, pc1, a0));
                u64 Ap = fma2(a2, ps2, mul2(a1, ps1));
                prodB = fma2(Bp, Bp, mul2(Br, Br));
                prodA = fma2(Ap, Ap, mul2(Ar, Ar));
            }
            {   // sections (4p+2, 4p+3)
                u64 b0 = cofp[0*8 + 2*p + 1], b1 = cofp[1*8 + 2*p + 1], b2 = cofp[2*8 + 2*p + 1];
                u64 a0 = cofp[3*8 + 2*p + 1], a1 = cofp[4*8 + 2*p + 1], a2 = cofp[5*8 + 2*p + 1];
                u64 Br = fma2(b2, pc2, fma2(b1, pc1, b0));
                u64 Bp = fma2(b2, ps2, mul2(b1, ps1));
                u64 Ar = fma2(a2, pc2, fma2(a1, pc1, a0));
                u64 Ap = fma2(a2, ps2, mul2(a1, ps1));
                prodB = mul2(prodB, fma2(Bp, Bp, mul2(Br, Br)));
                prodA = mul2(prodA, fma2(Ap, Ap, mul2(Ar, Ar)));
            }
            float al, ah; upk(prodA, al, ah);
            accR = mul2(accR, mul2(prodB, pk(frcp(al), frcp(ah))));
        }
        {
            float rlo, rhi; upk(accR, rlo, rhi);
            float pP  = rlo * rhi;                 // |H|^2
            float mag = fsqrt_ap(pP);
            float mpe = mag + EPS;
            float dB  = DB2 * flg2(mpe);
            pcc[ccslot] = KC * (dB - tgt) * (mag * frcp(mpe));
        }
        __syncthreads();

        // ---------- Pass 2 + fused update: warp s owns section s ----------
        {
            const int s = warp;
            float sb0 = cof[0][s], sb1 = cof[1][s], sb2 = cof[2][s];
            float sa0 = cof[3][s], sa1 = cof[4][s], sa2 = cof[5][s];
            u64 b0 = pk(sb0, sb0), b1 = pk(sb1, sb1), b2 = pk(sb2, sb2);
            u64 a0 = pk(sa0, sa0), a1 = pk(sa1, sa1), a2 = pk(sa2, sa2);
            u64 G0 = 0, G1 = 0, G2 = 0, H3 = 0, H4 = 0, H5 = 0;
#pragma unroll
            for (int k = 0; k < 8; ++k) {
                int f = k * 32 + lane;
                u64 c1 = tc1p[f], s1 = ts1p[f];
                u64 c2 = tc2p[f], s2 = ts2p[f];
                u64 cc = pccp[f];
                u64 Br = fma2(b2, c2, fma2(b1, c1, b0));
                u64 Bp = fma2(b2, s2, mul2(b1, s1));
                u64 Ar = fma2(a2, c2, fma2(a1, c1, a0));
                u64 Ap = fma2(a2, s2, mul2(a1, s1));
                u64 nB = fma2(Bp, Bp, mul2(Br, Br));
                u64 nA = fma2(Ap, Ap, mul2(Ar, Ar));
                // single reciprocal of the product serves both norms
                u64 prod = mul2(nB, nA);
                float pl, ph; upk(prod, pl, ph);
                u64 ccr = mul2(cc, pk(frcp(pl), frcp(ph)));
                u64 cB = mul2(ccr, nA);            // = cc/|B|^2
                u64 cA = mul2(ccr, nB);            // = cc/|A|^2 (positive)
                G0 = fma2(cB, Br, G0);
                G1 = fma2(cB, fma2(s1, Bp, mul2(c1, Br)), G1);  // c1*Br - s1*Bi
                G2 = fma2(cB, fma2(s2, Bp, mul2(c2, Br)), G2);
                H3 = fma2(cA, Ar, H3);
                H4 = fma2(cA, fma2(s1, Ap, mul2(c1, Ar)), H4);
                H5 = fma2(cA, fma2(s2, Ap, mul2(c2, Ar)), H5);
            }
            float g0, g1, g2, g3, g4, g5, u, v;
            upk(G0, u, v); g0 = u + v;
            upk(G1, u, v); g1 = u + v;
            upk(G2, u, v); g2 = u + v;
            upk(H3, u, v); g3 = -(u + v);
            upk(H4, u, v); g4 = -(u + v);
            upk(H5, u, v); g5 = -(u + v);
#pragma unroll
            for (int o = 16; o > 0; o >>= 1) {
                g0 += __shfl_xor_sync(0xffffffffu, g0, o);
                g1 += __shfl_xor_sync(0xffffffffu, g1, o);
                g2 += __shfl_xor_sync(0xffffffffu, g2, o);
                g3 += __shfl_xor_sync(0xffffffffu, g3, o);
                g4 += __shfl_xor_sync(0xffffffffu, g4, o);
                g5 += __shfl_xor_sync(0xffffffffu, g5, o);
            }
            // fused SGD update: lanes 0..5 update this section's coefficients
            if (lane < 6) {
                float gsel = g0;
                if (lane == 1) gsel = g1;
                if (lane == 2) gsel = g2;
                if (lane == 3) gsel = g3;
                if (lane == 4) gsel = g4;
                if (lane == 5) gsel = g5;
                cof[lane][s] -= LR * gsel;
            }
        }
        __syncthreads();
    }

    if (tid < 96) out[tid] = cof[tid % 6][tid / 6];
}

extern "C" void kernel_launch(void* const* d_in, const int* in_sizes, int n_in,
                              void* d_out, int out_size) {
    const float* sos_init  = (const float*)d_in[0];   // [16,6] = 96 floats
    const float* target_dB = (const float*)d_in[1];   // [512]
    float* out = (float*)d_out;                       // [16,6] = 96 floats
    sgd_filter_design_kernel<<<1, NT>>>(sos_init, target_dB, out);
}